// round 7
// baseline (speedup 1.0000x reference)
#include <cuda_runtime.h>
#include <cstdint>

#define BATCH 20
#define SEQ   4096
#define EMB   256
#define NB    32
#define BLK   128
#define CTX   384
#define MROWS (BATCH*SEQ)

#define SA 36      // A smem stride (floats) for staged pipeline: conflict-free
#define SB 136     // B smem stride (floats): conflict-free
#define ASTR 260   // resident-A stride (floats): bank = (4g+tig), conflict-free
#define ABUF (128*SA*4)                    // 18432 B per A stage
#define BBUF (32*SB*4)                     // 17408 B per B stage
#define SMEMB (3*ABUF + 3*BBUF + 512)      // 108032 B   (av/out)
#define ARES  (128*ASTR*4)                 // 133120 B resident A
#define SMEM_RES (ARES + 3*BBUF + 512)     // 185856 B   (qkv/qk)

// Scratch (device globals; no allocations allowed)
__device__ float g_wc[4*EMB*EMB];
__device__ float g_q [MROWS*EMB];
__device__ float g_kT[MROWS*EMB];                 // K transposed per block: [blk][emb][token]
__device__ float g_v [MROWS*EMB];
__device__ float g_p [(size_t)BATCH*NB*BLK*CTX];  // exp(logits), valid windows only
__device__ float g_l [MROWS];                     // softmax row sums
__device__ float g_att[MROWS*EMB];

// ---- primitives -----------------------------------------------------------

__device__ __forceinline__ uint32_t smem_u32(const void* p) {
    uint32_t a;
    asm("{ .reg .u64 t; cvta.to.shared.u64 t, %1; cvt.u32.u64 %0, t; }"
        : "=r"(a) : "l"(p));
    return a;
}

__device__ __forceinline__ float totf(float x) {
    uint32_t r;
    asm("cvt.rna.tf32.f32 %0, %1;" : "=r"(r) : "f"(x));
    return __uint_as_float(r);
}

__device__ __forceinline__ void cpa16(uint32_t dst, const float* src) {
    asm volatile("cp.async.cg.shared.global [%0], [%1], 16;" :: "r"(dst), "l"(src));
}
#define CP_COMMIT() asm volatile("cp.async.commit_group;" ::: "memory")
#define CP_WAIT1()  asm volatile("cp.async.wait_group 1;" ::: "memory")
#define CP_WAIT0()  asm volatile("cp.async.wait_group 0;" ::: "memory")

__device__ __forceinline__ void mma8(float c[4], float a0, float a1, float a2, float a3,
                                     float b0, float b1) {
    asm volatile(
        "mma.sync.aligned.m16n8k8.row.col.f32.tf32.tf32.f32 "
        "{%0,%1,%2,%3}, {%4,%5,%6,%7}, {%8,%9}, {%0,%1,%2,%3};"
        : "+f"(c[0]), "+f"(c[1]), "+f"(c[2]), "+f"(c[3])
        : "r"(__float_as_uint(a0)), "r"(__float_as_uint(a1)),
          "r"(__float_as_uint(a2)), "r"(__float_as_uint(a3)),
          "r"(__float_as_uint(b0)), "r"(__float_as_uint(b1)));
}

// ---- chunk copies ---------------------------------------------------------

__device__ __forceinline__ void cpA(uint32_t sA, const float* __restrict__ src,
                                    int ld, int t) {
#pragma unroll
    for (int j = 0; j < 4; j++) {
        int idx = j * 256 + t;
        int m = idx >> 3, k4 = (idx & 7) << 2;
        cpa16(sA + (uint32_t)(m * SA + k4) * 4, src + (size_t)m * ld + k4);
    }
}

__device__ __forceinline__ void cpB(uint32_t sB, const float* __restrict__ src,
                                    int ld, int t) {
#pragma unroll
    for (int j = 0; j < 4; j++) {
        int idx = j * 256 + t;
        int k = idx >> 5, n4 = (idx & 31) << 2;
        cpa16(sB + (uint32_t)(k * SB + n4) * 4, src + (size_t)k * ld + n4);
    }
}

// fill resident A: 128 rows x 256 cols (optionally tf32-rounding)
__device__ __forceinline__ void fillA(float* __restrict__ As,
                                      const float* __restrict__ src,
                                      bool cvt, int t) {
#pragma unroll
    for (int j = 0; j < 32; j++) {
        int idx = j * 256 + t;
        int m = idx >> 6, c4 = (idx & 63) << 2;
        float4 v = *(const float4*)(src + (size_t)m * EMB + c4);
        if (cvt) { v.x = totf(v.x); v.y = totf(v.y); v.z = totf(v.z); v.w = totf(v.w); }
        *(float4*)(As + m * ASTR + c4) = v;
    }
}

// ---- warp-tile compute for one 32-deep K chunk ----------------------------

__device__ __forceinline__ void mma_chunk(const float* __restrict__ As, int astr,
                                          const float* __restrict__ Bs,
                                          float acc[16][4], int t) {
    int lane = t & 31, w = t >> 5;
    int g = lane >> 2, tig = lane & 3;
    int mbase = (w >> 2) * 64 + g;
    int nbase = (w & 3) * 32 + g;
#pragma unroll
    for (int s = 0; s < 4; s++) {
        int k = s * 8 + tig;
        float b[4][2];
#pragma unroll
        for (int nt = 0; nt < 4; nt++) {
            b[nt][0] = Bs[k * SB + nbase + nt * 8];
            b[nt][1] = Bs[(k + 4) * SB + nbase + nt * 8];
        }
#pragma unroll
        for (int mt = 0; mt < 4; mt++) {
            int m = mbase + mt * 16;
            float a0 = As[m * astr + k];
            float a1 = As[(m + 8) * astr + k];
            float a2 = As[m * astr + k + 4];
            float a3 = As[(m + 8) * astr + k + 4];
#pragma unroll
            for (int nt = 0; nt < 4; nt++)
                mma8(acc[mt * 4 + nt], a0, a1, a2, a3, b[nt][0], b[nt][1]);
        }
    }
}

// ---- 3-stage A+B pipeline (av/out) ----------------------------------------

__device__ __forceinline__ void gemm_pipeline(const float* __restrict__ Abase, int aStep, int lda,
                                              const float* __restrict__ Bbase, int bStep, int ldb,
                                              int nC, float acc[16][4], char* smem, int t) {
    uint32_t aA[3], bA[3];
    const float* Ap[3];
    const float* Bp[3];
#pragma unroll
    for (int i = 0; i < 3; i++) {
        Ap[i] = (const float*)(smem + i * ABUF);
        Bp[i] = (const float*)(smem + 3 * ABUF + i * BBUF);
        aA[i] = smem_u32(Ap[i]);
        bA[i] = smem_u32(Bp[i]);
    }
    cpA(aA[0], Abase, lda, t);
    cpB(bA[0], Bbase, ldb, t);
    CP_COMMIT();
    cpA(aA[1], Abase + aStep, lda, t);
    cpB(bA[1], Bbase + (size_t)bStep, ldb, t);
    CP_COMMIT();

    int bufc = 0, bufn = 2;
    for (int c = 0; c < nC; c++) {
        if (c < nC - 1) CP_WAIT1(); else CP_WAIT0();
        __syncthreads();
        if (c + 2 < nC) {
            cpA(aA[bufn], Abase + (size_t)(c + 2) * aStep, lda, t);
            cpB(bA[bufn], Bbase + (size_t)(c + 2) * bStep, ldb, t);
            CP_COMMIT();
        }
        mma_chunk(Ap[bufc], SA, Bp[bufc], acc, t);
        bufc = (bufc == 2) ? 0 : bufc + 1;
        bufn = (bufn == 2) ? 0 : bufn + 1;
    }
}

// ---- B-only 3-stage pipeline with resident A (qkv/qk) ---------------------

__device__ __forceinline__ void gemm_resA(const float* __restrict__ As,
                                          const float* __restrict__ Bbase, int bStep, int ldb,
                                          int nC, float acc[16][4], char* bsm, int t) {
    uint32_t bA[3];
    const float* Bp[3];
#pragma unroll
    for (int i = 0; i < 3; i++) {
        Bp[i] = (const float*)(bsm + i * BBUF);
        bA[i] = smem_u32(Bp[i]);
    }
    cpB(bA[0], Bbase, ldb, t);
    CP_COMMIT();
    cpB(bA[1], Bbase + (size_t)bStep, ldb, t);
    CP_COMMIT();

    int bufc = 0, bufn = 2;
    for (int c = 0; c < nC; c++) {
        if (c < nC - 1) CP_WAIT1(); else CP_WAIT0();
        __syncthreads();
        if (c + 2 < nC) {
            cpB(bA[bufn], Bbase + (size_t)(c + 2) * bStep, ldb, t);
            CP_COMMIT();
        }
        mma_chunk(As + c * 32, ASTR, Bp[bufc], acc, t);
        bufc = (bufc == 2) ? 0 : bufc + 1;
        bufn = (bufn == 2) ? 0 : bufn + 1;
    }
}

// ---- standard epilogue ----------------------------------------------------

__device__ __forceinline__ void store_std(float acc[16][4], float* __restrict__ C, int ldc,
                                          const float* __restrict__ bias,
                                          bool rnd, int t) {
    int lane = t & 31, w = t >> 5;
    int g = lane >> 2, tig = lane & 3;
    int mbase = (w >> 2) * 64 + g;
    int nbase = (w & 3) * 32 + 2 * tig;
#pragma unroll
    for (int mt = 0; mt < 4; mt++) {
#pragma unroll
        for (int nt = 0; nt < 4; nt++) {
            float* c4 = acc[mt * 4 + nt];
            int m = mbase + mt * 16, n = nbase + nt * 8;
            float v0 = c4[0], v1 = c4[1], v2 = c4[2], v3 = c4[3];
            if (bias) { v0 += bias[n]; v1 += bias[n + 1]; v2 += bias[n]; v3 += bias[n + 1]; }
            if (rnd) { v0 = totf(v0); v1 = totf(v1); v2 = totf(v2); v3 = totf(v3); }
            *(float2*)(C + (size_t)m * ldc + n)       = make_float2(v0, v1);
            *(float2*)(C + (size_t)(m + 8) * ldc + n) = make_float2(v2, v3);
        }
    }
}

// ---- kernel 0: fused tf32-round of all four weights -----------------------

__global__ __launch_bounds__(256)
void wcvt_kernel(const float* __restrict__ Wq, const float* __restrict__ Wk,
                 const float* __restrict__ Wv, const float* __restrict__ Wo) {
    int i = blockIdx.x * 256 + threadIdx.x;       // over 4*16384 float4s
    int wsel = i >> 14, r = i & 16383;
    const float* src = (wsel == 0) ? Wq : (wsel == 1) ? Wk : (wsel == 2) ? Wv : Wo;
    float4 v = ((const float4*)src)[r];
    v.x = totf(v.x); v.y = totf(v.y); v.z = totf(v.z); v.w = totf(v.w);
    ((float4*)g_wc)[i] = v;
}

// ---- kernel 1: QKV projections (x resident in smem, z-loop) ---------------

__global__ __launch_bounds__(256, 1)
void qkv_mma(const float* __restrict__ x) {
    extern __shared__ char smbuf[];
    float* As = (float*)smbuf;
    char* bsm = smbuf + ARES;
    int t = threadIdx.x;
    int m0 = blockIdx.x * 128, n0 = blockIdx.y * 128;

    fillA(As, x + (size_t)m0 * EMB, true, t);     // rna-round x once, in smem

    for (int z = 0; z < 3; z++) {
        __syncthreads();                          // fill done / B bufs drained
        float acc[16][4] = {};
        gemm_resA(As, g_wc + (size_t)z * EMB * EMB + n0, 32 * EMB, EMB, 8, acc, bsm, t);

        if (z == 1) {
            // transposed store: g_kT[(n0+n)*128 + m] within this row-block
            float* KT = g_kT + (size_t)m0 * EMB + (size_t)n0 * 128;
            int lane = t & 31, w = t >> 5;
            int g = lane >> 2, tig = lane & 3;
            int mbase = (w >> 2) * 64 + g;
            int nbase = (w & 3) * 32 + 2 * tig;
#pragma unroll
            for (int mt = 0; mt < 4; mt++) {
#pragma unroll
                for (int nt = 0; nt < 4; nt++) {
                    float* c4 = acc[mt * 4 + nt];
                    int m = mbase + mt * 16, n = nbase + nt * 8;
                    KT[(size_t)n * 128 + m]           = totf(c4[0]);
                    KT[(size_t)(n + 1) * 128 + m]     = totf(c4[1]);
                    KT[(size_t)n * 128 + m + 8]       = totf(c4[2]);
                    KT[(size_t)(n + 1) * 128 + m + 8] = totf(c4[3]);
                }
            }
        } else {
            float* C = (z == 0 ? g_q : g_v) + (size_t)m0 * EMB + n0;
            store_std(acc, C, EMB, nullptr, true, t);
        }
    }
}

// ---- kernel 2: P = exp(Q@K^T/16), row sums (Q resident, cj-loop) ----------

__global__ __launch_bounds__(256, 1)
void qk_mma() {
    extern __shared__ char smbuf[];
    float* As = (float*)smbuf;
    char* bsm = smbuf + ARES;
    float* ls = (float*)(smbuf + ARES + 3 * BBUF);
    int t = threadIdx.x;
    int nbi = blockIdx.x, b = blockIdx.y;

    if (t < 128) ls[t] = 0.f;
    fillA(As, g_q + (size_t)(b * SEQ + nbi * BLK) * EMB, false, t);

    int lane = t & 31, w = t >> 5;
    int g = lane >> 2, tig = lane & 3;
    int mbase = (w >> 2) * 64 + g;
    int nbase = (w & 3) * 32 + 2 * tig;

    float rsum[8];
#pragma unroll
    for (int i = 0; i < 8; i++) rsum[i] = 0.f;

    int lo = (nbi == 0) ? 1 : 0;
    int hi = (nbi == NB - 1) ? 1 : 2;

    for (int cj = lo; cj <= hi; cj++) {
        __syncthreads();                          // fill done / B bufs drained
        int gb = nbi + cj - 1;
        float acc[16][4] = {};
        gemm_resA(As, g_kT + (size_t)(b * SEQ + gb * BLK) * EMB, 32 * 128, 128, 8,
                  acc, bsm, t);

        float* P = g_p + ((size_t)(b * NB + nbi) * BLK) * CTX + cj * BLK;
#pragma unroll
        for (int mt = 0; mt < 4; mt++) {
#pragma unroll
            for (int nt = 0; nt < 4; nt++) {
                float* c4 = acc[mt * 4 + nt];
                int m = mbase + mt * 16, n = nbase + nt * 8;
                float e0 = __expf(c4[0] * 0.0625f);
                float e1 = __expf(c4[1] * 0.0625f);
                float e2 = __expf(c4[2] * 0.0625f);
                float e3 = __expf(c4[3] * 0.0625f);
                rsum[mt * 2 + 0] += e0 + e1;
                rsum[mt * 2 + 1] += e2 + e3;
                *(float2*)(P + (size_t)m * CTX + n)       = make_float2(totf(e0), totf(e1));
                *(float2*)(P + (size_t)(m + 8) * CTX + n) = make_float2(totf(e2), totf(e3));
            }
        }
    }

#pragma unroll
    for (int i = 0; i < 8; i++) {
        rsum[i] += __shfl_xor_sync(0xFFFFFFFFu, rsum[i], 1);
        rsum[i] += __shfl_xor_sync(0xFFFFFFFFu, rsum[i], 2);
    }
    if (tig == 0) {
#pragma unroll
        for (int i = 0; i < 8; i++)
            atomicAdd(&ls[mbase + (i >> 1) * 16 + (i & 1) * 8], rsum[i]);
    }
    __syncthreads();
    float pad = 128.0f * (float)((nbi == 0) + (nbi == NB - 1));  // exp(0) keys
    if (t < 128)
        g_l[(size_t)(b * NB + nbi) * 128 + t] = ls[t] + pad;
}

// ---- kernel 3: O = (P @ Vc) / l, permuted store ---------------------------

__global__ __launch_bounds__(256, 2)
void av_mma() {
    extern __shared__ char smbuf[];
    int t = threadIdx.x;
    int nt0 = blockIdx.x, nbi = blockIdx.y, b = blockIdx.z;
    int n0 = nt0 * 128;

    int lo = (nbi == 0) ? 1 : 0;
    int hi = (nbi == NB - 1) ? 1 : 2;
    int nC = (hi - lo + 1) * 4;
    int gb0 = nbi + lo - 1;

    const float* Pb = g_p + (size_t)((b * NB + nbi) * BLK) * CTX + lo * 128;
    const float* Vb = g_v + (size_t)(b * SEQ + gb0 * BLK) * EMB + n0;

    float acc[16][4] = {};
    gemm_pipeline(Pb, 32, CTX, Vb, 32 * EMB, EMB, nC, acc, smbuf, t);

    const float* lrow = g_l + (size_t)(b * NB + nbi) * 128;
    int rowbase = nbi * (BATCH * BLK) + b * BLK;   // reference transpose (1,0,2,3)
    float* C = g_att + (size_t)rowbase * EMB + n0;

    int lane = t & 31, w = t >> 5;
    int g = lane >> 2, tig = lane & 3;
    int mbase = (w >> 2) * 64 + g;
    int nbase = (w & 3) * 32 + 2 * tig;
#pragma unroll
    for (int mt = 0; mt < 4; mt++) {
        int m = mbase + mt * 16;
        float inv0 = 1.0f / lrow[m];
        float inv1 = 1.0f / lrow[m + 8];
#pragma unroll
        for (int ntt = 0; ntt < 4; ntt++) {
            float* c4 = acc[mt * 4 + ntt];
            int n = nbase + ntt * 8;
            *(float2*)(C + (size_t)m * EMB + n) =
                make_float2(totf(c4[0] * inv0), totf(c4[1] * inv0));
            *(float2*)(C + (size_t)(m + 8) * EMB + n) =
                make_float2(totf(c4[2] * inv1), totf(c4[3] * inv1));
        }
    }
}

// ---- kernel 4: out = att @ Wo + bo ----------------------------------------

__global__ __launch_bounds__(256, 2)
void out_mma(const float* __restrict__ bo, float* __restrict__ out) {
    extern __shared__ char smbuf[];
    int t = threadIdx.x;
    int m0 = blockIdx.x * 128, n0 = blockIdx.y * 128;
    const float* W = g_wc + (size_t)3 * EMB * EMB;

    float acc[16][4] = {};
    gemm_pipeline(g_att + (size_t)m0 * EMB, 32, EMB,
                  W + n0, 32 * EMB, EMB, 8, acc, smbuf, t);
    store_std(acc, out + (size_t)m0 * EMB + n0, EMB, bo + n0, false, t);
}

// ---- launch ---------------------------------------------------------------

extern "C" void kernel_launch(void* const* d_in, const int* in_sizes, int n_in,
                              void* d_out, int out_size) {
    const float* x  = (const float*)d_in[0];
    const float* Wq = (const float*)d_in[1];
    const float* Wk = (const float*)d_in[2];
    const float* Wv = (const float*)d_in[3];
    const float* Wo = (const float*)d_in[4];
    const float* bo = (const float*)d_in[5];
    float* out = (float*)d_out;

    cudaFuncSetAttribute(qkv_mma, cudaFuncAttributeMaxDynamicSharedMemorySize, SMEM_RES);
    cudaFuncSetAttribute(qk_mma,  cudaFuncAttributeMaxDynamicSharedMemorySize, SMEM_RES);
    cudaFuncSetAttribute(av_mma,  cudaFuncAttributeMaxDynamicSharedMemorySize, SMEMB);
    cudaFuncSetAttribute(out_mma, cudaFuncAttributeMaxDynamicSharedMemorySize, SMEMB);

    wcvt_kernel<<<256, 256>>>(Wq, Wk, Wv, Wo);
    qkv_mma<<<dim3(MROWS / 128, EMB / 128), 256, SMEM_RES>>>(x);
    qk_mma<<<dim3(NB, BATCH), 256, SMEM_RES>>>();
    av_mma<<<dim3(2, NB, BATCH), 256, SMEMB>>>();
    out_mma<<<dim3(MROWS / 128, EMB / 128), 256, SMEMB>>>(bo, out);
}